// round 4
// baseline (speedup 1.0000x reference)
#include <cuda_runtime.h>
#include <cuda_bf16.h>
#include <math.h>

#define MAXN   8192
#define FDIM   128
#define HDIM   64
#define NB     48
#define TA     16        // atoms per feature block
#define MAXSEG 320       // max atoms per molecule (mean 128, sd ~11)
#define SPLIT  8         // blocks per molecule in pair kernel
#define QSCALE 3.7946016f   // sqrt(14.399)

// ---------------- device scratch (zero-initialized at module load) ----------
__device__ double g_energy;          // reset to 0 by last pair block each run
__device__ int    g_done;            // reset to 0 by last pair block each run
__device__ float  g_qsum[NB];        // reset to 0 by last pair block each run
__device__ float  g_q[MAXN];
__device__ float  g_sc6[MAXN];      // sqrt(softplus(c6_raw))
__device__ float  g_mu[MAXN * 3];
__device__ int    g_start[NB];
__device__ int    g_end[NB];

// ---------------- packed f32x2 helpers --------------------------------------
__device__ __forceinline__ unsigned long long pack2(float lo, float hi) {
    unsigned long long r;
    asm("mov.b64 %0, {%1, %2};" : "=l"(r) : "f"(lo), "f"(hi));
    return r;
}
__device__ __forceinline__ void unpack2(unsigned long long v, float& lo, float& hi) {
    asm("mov.b64 {%0, %1}, %2;" : "=f"(lo), "=f"(hi) : "l"(v));
}
__device__ __forceinline__ void ffma2(unsigned long long& d, unsigned long long a,
                                      unsigned long long b, unsigned long long c) {
    asm("fma.rn.f32x2 %0, %1, %2, %3;" : "=l"(d) : "l"(a), "l"(b), "l"(c));
}

// ================= features: q, sqrt(softplus(c6)), mu, qsum, seg bounds ====
// 128 threads, 16 atoms per block. Thread t: hidden unit t&63 of MLP t>>6.
__global__ __launch_bounds__(128) void features_kernel(
    const float* __restrict__ h0, const float* __restrict__ h1,
    const int*   __restrict__ batch,
    const float* __restrict__ qW1, const float* __restrict__ qb1,
    const float* __restrict__ qW2, const float* __restrict__ qb2,
    const float* __restrict__ cW1, const float* __restrict__ cb1,
    const float* __restrict__ cW2, const float* __restrict__ cb2,
    const float* __restrict__ muW, int N)
{
    int t  = threadIdx.x;          // 0..127
    int a0 = blockIdx.x * TA;

    // h0 transposed + atom-pair-packed: h0t[f*8 + ap] = {h0[a0+2ap][f], h0[a0+2ap+1][f]}
    __shared__ __align__(16) unsigned long long h0t[FDIM * (TA / 2)];  // 8 KB
    __shared__ float part[4][TA];

    // stage (thread t owns feature f = t; coalesced rows in global)
    {
        const float* base = h0 + (size_t)a0 * FDIM + t;
        #pragma unroll
        for (int ap = 0; ap < TA / 2; ap++) {
            float x0 = base[(2 * ap)     * FDIM];
            float x1 = base[(2 * ap + 1) * FDIM];
            h0t[t * (TA / 2) + ap] = pack2(x0, x1);
        }
    }

    // segment boundary detection (batch is sorted)
    if (t < TA) {
        int i  = a0 + t;
        int bi = batch[i];
        if (i == 0 || batch[i - 1] != bi) g_start[bi] = i;
        if (i == N - 1 || batch[i + 1] != bi) g_end[bi] = i + 1;
    }
    __syncthreads();

    int mlp = t >> 6;          // 0 = q, 1 = c
    int hu  = t & 63;
    int warp = t >> 5, lane = t & 31;
    const float* W1 = mlp ? cW1 : qW1;
    const float* B1 = mlp ? cb1 : qb1;
    const float* W2 = mlp ? cW2 : qW2;

    unsigned long long acc[TA / 2];
    #pragma unroll
    for (int ap = 0; ap < TA / 2; ap++) acc[ap] = 0ull;

    #pragma unroll 4
    for (int f = 0; f < FDIM; f++) {
        float w = W1[f * HDIM + hu];
        unsigned long long w2 = pack2(w, w);
        const ulonglong2* hp = (const ulonglong2*)&h0t[f * (TA / 2)];  // uniform -> broadcast
        ulonglong2 h01 = hp[0];
        ulonglong2 h23 = hp[1];
        ulonglong2 h45 = hp[2];
        ulonglong2 h67 = hp[3];
        ffma2(acc[0], h01.x, w2, acc[0]);
        ffma2(acc[1], h01.y, w2, acc[1]);
        ffma2(acc[2], h23.x, w2, acc[2]);
        ffma2(acc[3], h23.y, w2, acc[3]);
        ffma2(acc[4], h45.x, w2, acc[4]);
        ffma2(acc[5], h45.y, w2, acc[5]);
        ffma2(acc[6], h67.x, w2, acc[6]);
        ffma2(acc[7], h67.y, w2, acc[7]);
    }

    float b1v = B1[hu];
    float w2v = W2[hu];
    #pragma unroll
    for (int ap = 0; ap < TA / 2; ap++) {
        float p0, p1;
        unpack2(acc[ap], p0, p1);
        p0 += b1v; p1 += b1v;
        float v0 = (p0 / (1.0f + __expf(-p0))) * w2v;   // silu * W2
        float v1 = (p1 / (1.0f + __expf(-p1))) * w2v;
        #pragma unroll
        for (int off = 16; off >= 1; off >>= 1) {
            v0 += __shfl_xor_sync(0xffffffffu, v0, off);
            v1 += __shfl_xor_sync(0xffffffffu, v1, off);
        }
        if (lane == 0) {
            part[warp][2 * ap]     = v0;
            part[warp][2 * ap + 1] = v1;
        }
    }
    __syncthreads();

    if (t < 2 * TA) {
        int m2 = t >> 4, a = t & 15;    // m2: 0=q, 1=c
        float sum = part[2 * m2][a] + part[2 * m2 + 1][a];
        if (m2 == 0) {
            float q = sum + qb2[0];
            g_q[a0 + a] = q;
            atomicAdd(&g_qsum[batch[a0 + a]], q);
        } else {
            float c_raw = sum + cb2[0];
            float sp = (c_raw > 20.0f) ? c_raw : log1pf(__expf(c_raw));
            g_sc6[a0 + a] = sqrtf(sp);
        }
    }

    // mu[d] = h1[atom,d,:] . muW  -- 48 rows, 4 warps -> 12 rows each
    float mw0 = muW[lane], mw1 = muW[lane + 32];
    float mw2 = muW[lane + 64], mw3 = muW[lane + 96];
    for (int r = warp; r < 3 * TA; r += 4) {
        int atom = a0 + r / 3, d = r % 3;
        const float* row = h1 + ((size_t)atom * 3 + d) * FDIM;
        float v = row[lane] * mw0 + row[lane + 32] * mw1
                + row[lane + 64] * mw2 + row[lane + 96] * mw3;
        #pragma unroll
        for (int off = 16; off >= 1; off >>= 1)
            v += __shfl_xor_sync(0xffffffffu, v, off);
        if (lane == 0) g_mu[atom * 3 + d] = v;
    }
}

// ================= pairwise energy ==========================================
// 256 threads; SPLIT blocks per molecule. Warp owns rows i (boustrophedon),
// lanes stride over j > i. Staged as two float4 arrays.
__global__ __launch_bounds__(256) void pair_kernel(
    const float* __restrict__ pos, float* __restrict__ out)
{
    int b     = blockIdx.x / SPLIT;
    int slice = blockIdx.x % SPLIT;
    int t     = threadIdx.x;
    int warp  = t >> 5, lane = t & 31;

    __shared__ float4 sA[MAXSEG];   // {x, y, z, (q - qmean)*QSCALE}
    __shared__ float4 sB[MAXSEG];   // {mux, muy, muz, sqrt_c6}
    __shared__ float  ered[8];

    int s = g_start[b];
    int e = g_end[b];
    int m = e - s;
    if (m > MAXSEG) m = MAXSEG;

    float accE = 0.0f;
    if (m > 0) {
        float qmean = g_qsum[b] / (float)m;
        for (int k = t; k < m; k += 256) {
            int i = s + k;
            sA[k] = make_float4(pos[i * 3 + 0], pos[i * 3 + 1], pos[i * 3 + 2],
                                (g_q[i] - qmean) * QSCALE);
            sB[k] = make_float4(g_mu[i * 3 + 0], g_mu[i * 3 + 1], g_mu[i * 3 + 2],
                                g_sc6[i]);
        }
        __syncthreads();

        const int W = SPLIT * 8;             // 64 warps per molecule
        int wm = slice * 8 + warp;

        for (int k = 0; k * W < m; k++) {
            int i = (k & 1) ? ((k + 1) * W - 1 - wm) : (k * W + wm);
            if (i >= m - 1) continue;
            float4 Ai = sA[i];
            float4 Bi = sB[i];

            for (int j = i + 1 + lane; j < m; j += 32) {
                float4 Aj = sA[j];
                float4 Bj = sB[j];
                float dx = Ai.x - Aj.x;
                float dy = Ai.y - Aj.y;
                float dz = Ai.z - Aj.z;
                float d2 = fmaf(dx, dx, fmaf(dy, dy, dz * dz));
                float d2e = d2 + 1e-8f;
                float invd = rsqrtf(d2e);
                float dist = d2e * invd;

                // Coulomb (sqrt(14.399) folded into both q's)
                float taper = 1.0f - __expf(-0.5f * dist);
                float ev = Ai.w * Aj.w * invd * taper;

                // vdW
                float r6 = d2 * d2 * d2;
                ev -= __fdividef(Bi.w * Bj.w, r6 + 20.0f);

                // dipole-dipole
                float mm  = Bi.x * Bj.x + Bi.y * Bj.y + Bi.z * Bj.z;
                float mdi = Bi.x * dx + Bi.y * dy + Bi.z * dz;
                float mdj = Bj.x * dx + Bj.y * dy + Bj.z * dz;
                float num = mm - 3.0f * mdi * mdj * invd * invd;
                ev += __fdividef(num, d2 * dist + 10.0f);

                accE += ev;
            }
        }
    }

    // block reduce
    #pragma unroll
    for (int off = 16; off >= 1; off >>= 1)
        accE += __shfl_xor_sync(0xffffffffu, accE, off);
    if (lane == 0) ered[warp] = accE;
    __syncthreads();

    if (t == 0) {
        float tot = 0.0f;
        #pragma unroll
        for (int w = 0; w < 8; w++) tot += ered[w];
        atomicAdd(&g_energy, (double)tot);
        __threadfence();
        int done = atomicAdd(&g_done, 1);
        if (done == (int)gridDim.x - 1) {
            out[0] = (float)g_energy;
            // restore pristine state for the next graph replay
            g_energy = 0.0;
            g_done   = 0;
            #pragma unroll
            for (int i = 0; i < NB; i++) g_qsum[i] = 0.0f;
        }
    }
}

// ---------------- launch ----------------
extern "C" void kernel_launch(void* const* d_in, const int* in_sizes, int n_in,
                              void* d_out, int out_size)
{
    const float* h0    = (const float*)d_in[0];
    const float* h1    = (const float*)d_in[1];
    const float* pos   = (const float*)d_in[2];
    const int*   batch = (const int*)  d_in[3];
    const float* qW1   = (const float*)d_in[4];
    const float* qb1   = (const float*)d_in[5];
    const float* qW2   = (const float*)d_in[6];
    const float* qb2   = (const float*)d_in[7];
    const float* cW1   = (const float*)d_in[8];
    const float* cb1   = (const float*)d_in[9];
    const float* cW2   = (const float*)d_in[10];
    const float* cb2   = (const float*)d_in[11];
    const float* muW   = (const float*)d_in[12];

    int N = in_sizes[3];

    features_kernel<<<N / TA, 128>>>(h0, h1, batch, qW1, qb1, qW2, qb2,
                                     cW1, cb1, cW2, cb2, muW, N);
    pair_kernel<<<NB * SPLIT, 256>>>(pos, (float*)d_out);
}

// round 5
// speedup vs baseline: 1.1663x; 1.1663x over previous
#include <cuda_runtime.h>
#include <cuda_bf16.h>
#include <math.h>

#define MAXN   8192
#define FDIM   128
#define HDIM   64
#define NB     48
#define TA     8         // atoms per feature block
#define MAXSEG 320       // max atoms per molecule (mean 128, sd ~11)
#define SPLIT  8         // blocks per molecule in pair kernel
#define QSCALE 3.7946016f   // sqrt(14.399)

// ---------------- device scratch (zero-initialized; restored each replay) ---
__device__ float  g_emol[NB];
__device__ int    g_mdone[NB];
__device__ int    g_done;
__device__ float  g_q[MAXN];
__device__ float  g_sc6[MAXN];      // sqrt(softplus(c6_raw))
__device__ float  g_mu[MAXN * 3];
__device__ int    g_start[NB];
__device__ int    g_end[NB];

// ---------------- f32x2 helpers ----------------------------------------------
__device__ __forceinline__ unsigned long long pack2(float lo, float hi) {
    unsigned long long r;
    asm("mov.b64 %0, {%1, %2};" : "=l"(r) : "f"(lo), "f"(hi));
    return r;
}
__device__ __forceinline__ void unpack2(unsigned long long v, float& lo, float& hi) {
    asm("mov.b64 {%0, %1}, %2;" : "=f"(lo), "=f"(hi) : "l"(v));
}
__device__ __forceinline__ void ffma2(unsigned long long& d, unsigned long long a,
                                      unsigned long long b, unsigned long long c) {
    asm("fma.rn.f32x2 %0, %1, %2, %3;" : "=l"(d) : "l"(a), "l"(b), "l"(c));
}
// load 16B of shared as two b64 (f32x2 pairs), no repacking
__device__ __forceinline__ void lds_v2_u64(unsigned long long& a, unsigned long long& b,
                                           unsigned int smem_addr) {
    asm("ld.shared.v2.u64 {%0, %1}, [%2];" : "=l"(a), "=l"(b) : "r"(smem_addr));
}

// ================= features: q, sqrt(softplus(c6)), mu, segment bounds ======
// 128 threads, 8 atoms per block. Thread t: hidden unit t&63 of MLP t>>6.
__global__ __launch_bounds__(128) void features_kernel(
    const float* __restrict__ h0, const float* __restrict__ h1,
    const int*   __restrict__ batch,
    const float* __restrict__ qW1, const float* __restrict__ qb1,
    const float* __restrict__ qW2, const float* __restrict__ qb2,
    const float* __restrict__ cW1, const float* __restrict__ cb1,
    const float* __restrict__ cW2, const float* __restrict__ cb2,
    const float* __restrict__ muW, int N)
{
    int t  = threadIdx.x;          // 0..127
    int a0 = blockIdx.x * TA;

    __shared__ __align__(16) float h0s[TA][FDIM];    // 4 KB
    __shared__ float part[4][TA];

    // stage h0 tile: 8*128 floats = 256 float4, 128 threads -> 2 each (coalesced)
    {
        const float4* src = (const float4*)(h0 + (size_t)a0 * FDIM);
        float4* dst = (float4*)&h0s[0][0];
        dst[t]       = src[t];
        dst[t + 128] = src[t + 128];
    }

    // segment boundary detection (batch is sorted)
    if (t < TA) {
        int i  = a0 + t;
        int bi = batch[i];
        if (i == 0 || batch[i - 1] != bi) g_start[bi] = i;
        if (i == N - 1 || batch[i + 1] != bi) g_end[bi] = i + 1;
    }
    __syncthreads();

    int mlp = t >> 6;          // 0 = q, 1 = c
    int hu  = t & 63;
    int warp = t >> 5, lane = t & 31;
    const float* W1 = mlp ? cW1 : qW1;
    const float* B1 = mlp ? cb1 : qb1;
    const float* W2 = mlp ? cW2 : qW2;

    unsigned int h0s_base = (unsigned int)__cvta_generic_to_shared(&h0s[0][0]);

    // acc[a] holds {sum over even-pair f, sum over odd-pair f} packed f32x2
    unsigned long long acc[TA];
    #pragma unroll
    for (int a = 0; a < TA; a++) acc[a] = 0ull;

    #pragma unroll 4
    for (int f0 = 0; f0 < FDIM; f0 += 4) {
        const float* wp = W1 + f0 * HDIM + hu;
        float wa = wp[0];
        float wb = wp[HDIM];
        float wc = wp[2 * HDIM];
        float wd = wp[3 * HDIM];
        unsigned long long w01 = pack2(wa, wb);
        unsigned long long w23 = pack2(wc, wd);
        unsigned int addr = h0s_base + f0 * 4;
        #pragma unroll
        for (int a = 0; a < TA; a++) {
            unsigned long long h01, h23;
            lds_v2_u64(h01, h23, addr + a * (FDIM * 4));  // uniform -> broadcast
            ffma2(acc[a], h01, w01, acc[a]);
            ffma2(acc[a], h23, w23, acc[a]);
        }
    }

    float b1v = B1[hu];
    float w2v = W2[hu];
    #pragma unroll
    for (int a = 0; a < TA; a++) {
        float p0, p1;
        unpack2(acc[a], p0, p1);
        float pre = p0 + p1 + b1v;
        float v   = (pre / (1.0f + __expf(-pre))) * w2v;   // silu * W2
        #pragma unroll
        for (int off = 16; off >= 1; off >>= 1)
            v += __shfl_xor_sync(0xffffffffu, v, off);
        if (lane == 0) part[warp][a] = v;
    }
    __syncthreads();

    if (t < 2 * TA) {
        int m2 = t >> 3, a = t & 7;    // m2: 0=q, 1=c
        float sum = part[2 * m2][a] + part[2 * m2 + 1][a];
        if (m2 == 0) {
            g_q[a0 + a] = sum + qb2[0];
        } else {
            float c_raw = sum + cb2[0];
            float sp = (c_raw > 20.0f) ? c_raw : log1pf(__expf(c_raw));
            g_sc6[a0 + a] = sqrtf(sp);
        }
    }

    // mu[d] = h1[atom,d,:] . muW  -- 24 rows, 4 warps -> 6 rows each
    float mw0 = muW[lane], mw1 = muW[lane + 32];
    float mw2 = muW[lane + 64], mw3 = muW[lane + 96];
    for (int r = warp; r < 3 * TA; r += 4) {
        int atom = a0 + r / 3, d = r % 3;
        const float* row = h1 + ((size_t)atom * 3 + d) * FDIM;
        float v = row[lane] * mw0 + row[lane + 32] * mw1
                + row[lane + 64] * mw2 + row[lane + 96] * mw3;
        #pragma unroll
        for (int off = 16; off >= 1; off >>= 1)
            v += __shfl_xor_sync(0xffffffffu, v, off);
        if (lane == 0) g_mu[atom * 3 + d] = v;
    }
}

// ================= pairwise energy ==========================================
// 256 threads; SPLIT blocks per molecule. Warp owns rows i (boustrophedon),
// lanes stride over j > i.
__global__ __launch_bounds__(256) void pair_kernel(
    const float* __restrict__ pos, float* __restrict__ out)
{
    int b     = blockIdx.x / SPLIT;
    int slice = blockIdx.x % SPLIT;
    int t     = threadIdx.x;
    int warp  = t >> 5, lane = t & 31;

    __shared__ float4 sA[MAXSEG];   // {x, y, z, (q - qmean)*QSCALE}
    __shared__ float4 sB[MAXSEG];   // {mux, muy, muz, sqrt_c6}
    __shared__ float  wred[8];
    __shared__ float  s_qmeanS;

    int s = g_start[b];
    int e = g_end[b];
    int m = e - s;
    if (m > MAXSEG) m = MAXSEG;

    float accE = 0.0f;
    if (m > 0) {
        for (int k = t; k < m; k += 256) {
            int i = s + k;
            sA[k] = make_float4(pos[i * 3 + 0], pos[i * 3 + 1], pos[i * 3 + 2],
                                g_q[i] * QSCALE);
            sB[k] = make_float4(g_mu[i * 3 + 0], g_mu[i * 3 + 1], g_mu[i * 3 + 2],
                                g_sc6[i]);
        }
        __syncthreads();

        // scaled q mean over segment
        float ls = 0.0f;
        for (int k = t; k < m; k += 256) ls += sA[k].w;
        #pragma unroll
        for (int off = 16; off >= 1; off >>= 1)
            ls += __shfl_xor_sync(0xffffffffu, ls, off);
        if (lane == 0) wred[warp] = ls;
        __syncthreads();
        if (t == 0) {
            float tot = 0.0f;
            #pragma unroll
            for (int w = 0; w < 8; w++) tot += wred[w];
            s_qmeanS = tot / (float)m;
        }
        __syncthreads();
        float qmeanS = s_qmeanS;
        for (int k = t; k < m; k += 256) sA[k].w -= qmeanS;
        __syncthreads();

        const int W = SPLIT * 8;             // 64 warps per molecule
        int wm = slice * 8 + warp;

        for (int k = 0; k * W < m; k++) {
            int i = (k & 1) ? ((k + 1) * W - 1 - wm) : (k * W + wm);
            if (i >= m - 1) continue;
            float4 Ai = sA[i];
            float4 Bi = sB[i];

            for (int j = i + 1 + lane; j < m; j += 32) {
                float4 Aj = sA[j];
                float4 Bj = sB[j];
                float dx = Ai.x - Aj.x;
                float dy = Ai.y - Aj.y;
                float dz = Ai.z - Aj.z;
                float d2 = fmaf(dx, dx, fmaf(dy, dy, dz * dz));
                float d2e = d2 + 1e-8f;
                float invd = rsqrtf(d2e);
                float dist = d2e * invd;

                // Coulomb (sqrt(14.399) folded into both q's)
                float taper = 1.0f - __expf(-0.5f * dist);
                float ev = Ai.w * Aj.w * invd * taper;

                // vdW
                float r6 = d2 * d2 * d2;
                ev -= __fdividef(Bi.w * Bj.w, r6 + 20.0f);

                // dipole-dipole
                float mm  = Bi.x * Bj.x + Bi.y * Bj.y + Bi.z * Bj.z;
                float mdi = Bi.x * dx + Bi.y * dy + Bi.z * dz;
                float mdj = Bj.x * dx + Bj.y * dy + Bj.z * dz;
                float num = mm - 3.0f * mdi * mdj * invd * invd;
                ev += __fdividef(num, d2 * dist + 10.0f);

                accE += ev;
            }
        }
    }

    // block reduce
    #pragma unroll
    for (int off = 16; off >= 1; off >>= 1)
        accE += __shfl_xor_sync(0xffffffffu, accE, off);
    __syncthreads();          // wred reuse
    if (lane == 0) wred[warp] = accE;
    __syncthreads();

    if (t == 0) {
        float tot = 0.0f;
        #pragma unroll
        for (int w = 0; w < 8; w++) tot += wred[w];

        // hierarchical endgame: per-molecule accumulator + tickets
        atomicAdd(&g_emol[b], tot);
        __threadfence();
        if (atomicAdd(&g_mdone[b], 1) == SPLIT - 1) {
            __threadfence();
            if (atomicAdd(&g_done, 1) == NB - 1) {
                __threadfence();
                double E = 0.0;
                #pragma unroll
                for (int i = 0; i < NB; i++) E += (double)g_emol[i];
                out[0] = (float)E;
                // restore pristine state for the next graph replay
                #pragma unroll
                for (int i = 0; i < NB; i++) { g_emol[i] = 0.0f; g_mdone[i] = 0; }
                g_done = 0;
            }
        }
    }
}

// ---------------- launch ----------------
extern "C" void kernel_launch(void* const* d_in, const int* in_sizes, int n_in,
                              void* d_out, int out_size)
{
    const float* h0    = (const float*)d_in[0];
    const float* h1    = (const float*)d_in[1];
    const float* pos   = (const float*)d_in[2];
    const int*   batch = (const int*)  d_in[3];
    const float* qW1   = (const float*)d_in[4];
    const float* qb1   = (const float*)d_in[5];
    const float* qW2   = (const float*)d_in[6];
    const float* qb2   = (const float*)d_in[7];
    const float* cW1   = (const float*)d_in[8];
    const float* cb1   = (const float*)d_in[9];
    const float* cW2   = (const float*)d_in[10];
    const float* cb2   = (const float*)d_in[11];
    const float* muW   = (const float*)d_in[12];

    int N = in_sizes[3];

    features_kernel<<<N / TA, 128>>>(h0, h1, batch, qW1, qb1, qW2, qb2,
                                     cW1, cb1, cW2, cb2, muW, N);
    pair_kernel<<<NB * SPLIT, 256>>>(pos, (float*)d_out);
}